// round 17
// baseline (speedup 1.0000x reference)
#include <cuda_runtime.h>

// DFMB PS ROI Align for GB300. C=10, PH=PW=7 (P=49), H=W=34, S=4, N=16384.
//
// R17 strategy (wavefront-oriented rework of R15):
//  - transpose feature map to [p][y][x][c_pad16]  (64B/position, CP=16;
//    padding shares lines with real data -> free in wavefront terms)
//  - separable 4x4 subsample bilinear -> per-bin wx[4], wy[4]
//  - phase 1 (1 thread/bin): geometry ONCE; emit per-ROW entries
//    {wy*invc, rowbase} for wy!=0 rows (avg ~2.7) + wx[4] + outb
//  - phase 2 (16 lanes/bin, lane = (position, channel-chunk)): one
//    LDG.128 per row per 16-lane group loads the whole 256B row
//    (2-3 lines vs 8 scattered); guarded-unroll pipeline hoists row
//    loads ahead of FMAs; shfl_xor(4)+shfl_xor(8) butterfly reduces
//    the 4 positions per channel chunk. Zero-weight columns multiply
//    finite in-array or zero-pad data -> contribute exact 0.

#define NC   10
#define CP   16        // padded channel stride (64B per position)
#define NPH  7
#define NPW  7
#define NP   49
#define NH   34
#define NW   34
#define NHW  1156
#define ROWSTRIDE (NW * CP)   // 544 floats

// +256 floats zero pad: unconditional 4-column row loads can overrun the
// last valid row by <64 elements; pad is zero-init and never written.
__device__ float g_ft_t[NP * NHW * CP + 256];

// ---------------------------------------------------------------------------
// Kernel 1: transpose [C][P][H*W] -> [P][H*W][CP], zero pad c>=10
// ---------------------------------------------------------------------------
__global__ __launch_bounds__(256) void transpose_kernel(const float* __restrict__ ft) {
    int idx = blockIdx.x * 256 + threadIdx.x;
    const int total = NP * NHW * CP;
    if (idx >= total) return;
    int c    = idx & (CP - 1);
    int rest = idx >> 4;
    int yx   = rest % NHW;
    int p    = rest / NHW;
    float v = 0.0f;
    if (c < NC) v = ft[(c * NP + p) * NHW + yx];
    g_ft_t[idx] = v;
}

// ---------------------------------------------------------------------------
// Kernel 2: main ROI align
// ---------------------------------------------------------------------------
struct __align__(16) Bin2 {
    float2 rows[4];      // {wy*invc, rowbase elem offset (bit-cast)}
    float4 wx;           // column weights
    int nr;              // number of active rows (0..4)
    int outb;            // n*490 + p, or -1
    int pad0, pad1;
};                        // 64 B stride

#define FMAR(rr, vv) { \
    float w_ = rr.x * wxp; \
    a0 = fmaf(w_, vv.x, a0); a1 = fmaf(w_, vv.y, a1); \
    a2 = fmaf(w_, vv.z, a2); a3 = fmaf(w_, vv.w, a3); }

#define LOADR(rr, vv, idx) \
    rr = b.rows[idx]; \
    vv = *(const float4*)(src + __float_as_int(rr.y));

__global__ __launch_bounds__(256, 4) void roi_kernel(const float* __restrict__ rois,
                                                     float* __restrict__ out,
                                                     int nbins) {
    __shared__ Bin2 sb[256];             // 16384 B
    const int tid = threadIdx.x;
    const int bin = blockIdx.x * 256 + tid;

    // ---------------- Phase 1: per-bin geometry -> row entries ------------
    {
        Bin2 bi;
        bi.nr = 0; bi.outb = -1;

        if (bin < nbins) {
            int n  = bin / NP;
            int p  = bin - n * NP;
            int ph = p / NPW;
            int pw = p - ph * NPW;

            const float* r = rois + n * 5;
            float rsw = r[1] * 0.0625f;
            float rsh = r[2] * 0.0625f;
            float rew = r[3] * 0.0625f;
            float reh = r[4] * 0.0625f;

            float roi_h = reh - rsh; roi_h = (roi_h > 0.1f) ? roi_h : 0.1f;
            float roi_w = rew - rsw; roi_w = (roi_w > 0.1f) ? roi_w : 0.1f;
            float bin_h = roi_h / 7.0f;
            float bin_w = roi_w / 7.0f;
            float sub_h = bin_h * 0.25f;
            float sub_w = bin_w * 0.25f;

            // no FMA contraction: floor() boundary must match reference
            float hstart = floorf(__fadd_rn(rsh, __fmul_rn((float)ph, bin_h)));
            float wstart = floorf(__fadd_rn(rsw, __fmul_rn((float)pw, bin_w)));

            float wx0 = 0.f, wx1 = 0.f, wx2 = 0.f, wx3 = 0.f;
            float wy0 = 0.f, wy1 = 0.f, wy2 = 0.f, wy3 = 0.f;

            // ---- X direction ----
            float ckx = 0.0f;
            int ax = 0;
            #pragma unroll
            for (int j = 0; j < 4; j++) {
                float w   = __fadd_rn(wstart, __fmul_rn((float)j + 0.5f, sub_w));
                float x1f = floorf(w);
                float x2f = ceilf(w);
                int x1 = (int)x1f; x1 = max(0, min(NW - 1, x1));
                int x2 = (int)x2f; x2 = max(0, min(NW - 1, x2));
                if (j == 0) ax = x1;   // window origin; corners land in [ax, ax+3]
                float kx  = (w > -1.0f && w < (float)NW) ? 1.0f : 0.0f;
                float x1v = (x1f >= 0.0f && x1f < (float)NW) ? kx : 0.0f;
                float x2v = (x2f >= 0.0f && x2f < (float)NW) ? kx : 0.0f;
                float dx  = w - (float)x1;       // vs CLAMPED corner (ref semantics)
                float wa  = x1v * (1.0f - dx);
                float wb  = x2v * dx;
                int s1 = x1 - ax, s2 = x2 - ax;
                wx0 += (s1 == 0 ? wa : 0.f) + (s2 == 0 ? wb : 0.f);
                wx1 += (s1 == 1 ? wa : 0.f) + (s2 == 1 ? wb : 0.f);
                wx2 += (s1 == 2 ? wa : 0.f) + (s2 == 2 ? wb : 0.f);
                wx3 += (s1 == 3 ? wa : 0.f) + (s2 == 3 ? wb : 0.f);
                ckx += kx;
            }

            // ---- Y direction ----
            float cky = 0.0f;
            int by = 0;
            #pragma unroll
            for (int j = 0; j < 4; j++) {
                float h   = __fadd_rn(hstart, __fmul_rn((float)j + 0.5f, sub_h));
                float y1f = floorf(h);
                float y2f = ceilf(h);
                int y1 = (int)y1f; y1 = max(0, min(NH - 1, y1));
                int y2 = (int)y2f; y2 = max(0, min(NH - 1, y2));
                if (j == 0) by = y1;
                float ky  = (h > -1.0f && h < (float)NH) ? 1.0f : 0.0f;
                float y1v = (y1f >= 0.0f && y1f < (float)NH) ? ky : 0.0f;
                float y2v = (y2f >= 0.0f && y2f < (float)NH) ? ky : 0.0f;
                float dy  = h - (float)y1;
                float wa  = y1v * (1.0f - dy);
                float wb  = y2v * dy;
                int s1 = y1 - by, s2 = y2 - by;
                wy0 += (s1 == 0 ? wa : 0.f) + (s2 == 0 ? wb : 0.f);
                wy1 += (s1 == 1 ? wa : 0.f) + (s2 == 1 ? wb : 0.f);
                wy2 += (s1 == 2 ? wa : 0.f) + (s2 == 2 ? wb : 0.f);
                wy3 += (s1 == 3 ? wa : 0.f) + (s2 == 3 ? wb : 0.f);
                cky += ky;
            }

            float count = ckx * cky;
            float denom = (count > 0.0f) ? count : 1.0f;
            float invc  = 1.0f / denom;
            int   boff  = (p * NHW + by * NW + ax) * CP;
            bi.outb     = n * (NC * NP) + p;
            bi.wx       = make_float4(wx0, wx1, wx2, wx3);

            float wys[4] = {wy0, wy1, wy2, wy3};
            int nr = 0;
            #pragma unroll
            for (int rr = 0; rr < 4; rr++) {
                float wyr = wys[rr] * invc;
                if (wyr != 0.0f) {
                    bi.rows[nr] = make_float2(
                        wyr, __int_as_float(boff + rr * ROWSTRIDE));
                    nr++;
                }
            }
            bi.nr = nr;
        }
        sb[tid] = bi;
    }
    __syncthreads();

    // ---------------- Phase 2: 16-lane row gather + shuffle reduce --------
    const int wid   = tid >> 5;
    const int lane  = tid & 31;
    const int g     = lane >> 4;        // 16-lane group 0/1
    const int pos   = (lane >> 2) & 3;  // window column 0..3
    const int chunk = lane & 3;         // channel chunk (4 floats)
    const float* src = g_ft_t + (lane & 15) * 4;   // + pos*64B + chunk*16B

    #pragma unroll 1
    for (int pass = 0; pass < 16; pass++) {
        const int slot = pass * 16 + wid * 2 + g;   // consecutive bins/warp
        const Bin2& b = sb[slot];
        const int nr = b.nr;
        const float wxp = (pos == 0) ? b.wx.x : (pos == 1) ? b.wx.y
                        : (pos == 2) ? b.wx.z : b.wx.w;
        float a0 = 0.f, a1 = 0.f, a2 = 0.f, a3 = 0.f;

        if (nr > 0) {
            float2 r0, r1, r2, r3;
            float4 v0, v1, v2, v3;
            LOADR(r0, v0, 0)
            if (nr > 1) {
                LOADR(r1, v1, 1)
                FMAR(r0, v0)
                if (nr > 2) {
                    LOADR(r2, v2, 2)
                    FMAR(r1, v1)
                    if (nr > 3) {
                        LOADR(r3, v3, 3)
                        FMAR(r2, v2)
                        FMAR(r3, v3)
                    } else {
                        FMAR(r2, v2)
                    }
                } else {
                    FMAR(r1, v1)
                }
            } else {
                FMAR(r0, v0)
            }
        }

        // butterfly over the 4 positions (lane bits 2,3)
        a0 += __shfl_xor_sync(0xffffffffu, a0, 4);
        a1 += __shfl_xor_sync(0xffffffffu, a1, 4);
        a2 += __shfl_xor_sync(0xffffffffu, a2, 4);
        a3 += __shfl_xor_sync(0xffffffffu, a3, 4);
        a0 += __shfl_xor_sync(0xffffffffu, a0, 8);
        a1 += __shfl_xor_sync(0xffffffffu, a1, 8);
        a2 += __shfl_xor_sync(0xffffffffu, a2, 8);
        a3 += __shfl_xor_sync(0xffffffffu, a3, 8);

        const int ob = b.outb;
        if (ob >= 0 && pos == 0 && chunk < 3) {
            float* o = out + ob + chunk * 4 * NP;
            o[0]  = a0;                    // c = 4*chunk
            o[NP] = a1;                    // c = 4*chunk+1
            if (chunk < 2) {
                o[2 * NP] = a2;            // c = 4*chunk+2
                o[3 * NP] = a3;            // c = 4*chunk+3
            }
        }
    }
}

// ---------------------------------------------------------------------------
extern "C" void kernel_launch(void* const* d_in, const int* in_sizes, int n_in,
                              void* d_out, int out_size) {
    const float* ft   = (const float*)d_in[0];   // (1, 490, 34, 34)
    const float* rois = (const float*)d_in[1];   // (N, 5)
    float* out = (float*)d_out;                  // (N, 10, 49)

    int N = in_sizes[1] / 5;
    int nbins = N * NP;

    {
        const int total = NP * NHW * CP;
        transpose_kernel<<<(total + 255) / 256, 256>>>(ft);
    }
    {
        roi_kernel<<<(nbins + 255) / 256, 256>>>(rois, out, nbins);
    }
}